// round 6
// baseline (speedup 1.0000x reference)
#include <cuda_runtime.h>
#include <cuda_bf16.h>

#define QN 64
#define AN 32
#define BN 256
#define SN 2048
#define MAXSTEP 520

// Interleaved bf16 layout for a 64x64 matrix W: element (i,j) at
//   bf16 index  (i>>3)*512 + j*8 + (i&7)
// One 16B granule = rows 8c..8c+7 of column j.
__device__ __align__(16) static __nv_bfloat16 g_pairs  [1024 * 4096];  // P[a0*32+a1]
__device__ __align__(16) static __nv_bfloat16 g_pairsT [1024 * 4096];  // P^T
__device__ __align__(16) static __nv_bfloat16 g_singles [32 * 4096];   // W[a]
__device__ __align__(16) static __nv_bfloat16 g_singlesT[32 * 4096];   // W[a]^T
__device__ __align__(16) static float g_Wf[32 * 4096];                 // f32 W[a]
__device__ static short g_order[BN];                                   // ids, desc length

// ---------------------------------------------------------------------------
// Kernel 1: W[a][i][j] = softmax_j(T_logits[i][a][:]). One warp per (i,a).
// ---------------------------------------------------------------------------
__global__ void k_softmax(const float* __restrict__ T) {
    int warp = (blockIdx.x << 2) + (threadIdx.x >> 5);   // warp = i*32 + a
    int lane = threadIdx.x & 31;
    int i = warp >> 5, a = warp & 31;
    const float* row = T + warp * 64;
    float v0 = row[lane], v1 = row[lane + 32];
    float m = fmaxf(v0, v1);
#pragma unroll
    for (int o = 16; o; o >>= 1) m = fmaxf(m, __shfl_xor_sync(0xFFFFFFFFu, m, o));
    float e0 = expf(v0 - m), e1 = expf(v1 - m);
    float s = e0 + e1;
#pragma unroll
    for (int o = 16; o; o >>= 1) s += __shfl_xor_sync(0xFFFFFFFFu, s, o);
    float inv = 1.0f / s;
    float w0 = e0 * inv, w1 = e1 * inv;

    float* wf = g_Wf + a * 4096 + i * 64;
    wf[lane] = w0;
    wf[lane + 32] = w1;

    __nv_bfloat16* sg  = g_singles  + a * 4096;
    __nv_bfloat16* sgT = g_singlesT + a * 4096;
    int c = i >> 3, r = i & 7;
    int j0 = lane, j1 = lane + 32;
    sg[c * 512 + j0 * 8 + r] = __float2bfloat16(w0);
    sg[c * 512 + j1 * 8 + r] = __float2bfloat16(w1);
    sgT[(j0 >> 3) * 512 + i * 8 + (j0 & 7)] = __float2bfloat16(w0);
    sgT[(j1 >> 3) * 512 + i * 8 + (j1 & 7)] = __float2bfloat16(w1);
}

// ---------------------------------------------------------------------------
// Kernel 1b: rank-sort sequence ids by length descending.
// ---------------------------------------------------------------------------
__global__ void k_sort(const int* __restrict__ lengths) {
    __shared__ int Ls[BN];
    int t = threadIdx.x;
    int L = lengths[t];
    Ls[t] = L;
    __syncthreads();
    int rank = 0;
#pragma unroll 8
    for (int i = 0; i < BN; i++) {
        int Li = Ls[i];
        rank += (Li > L) || (Li == L && i < t);
    }
    g_order[rank] = (short)t;
}

// ---------------------------------------------------------------------------
// Kernel 2: P = W[a0]@W[a1]; writes bf16 interleaved P AND P^T.
// 1024 CTAs x 128 threads, 8x4 register tiles, smem round-trip for transpose.
// ---------------------------------------------------------------------------
__device__ __forceinline__ unsigned packbf(float a, float b) {
    __nv_bfloat162 h = __floats2bfloat162_rn(a, b);
    return *(unsigned*)&h;
}

__global__ void k_pairs() {
    __shared__ __align__(16) float As[64][68];   // As[k][i] = A[i][k]; reused as Out[i][j]
    __shared__ __align__(16) float Bs[64][64];   // Bs[k][j] = B[k][j]
    int mId = blockIdx.x;
    int a0 = mId >> 5, a1 = mId & 31;
    const float* A  = g_Wf + a0 * 4096;
    const float* Bm = g_Wf + a1 * 4096;
    int t = threadIdx.x;
    for (int idx = t; idx < 4096; idx += 128) {
        As[idx & 63][idx >> 6] = A[idx];
        Bs[idx >> 6][idx & 63] = Bm[idx];
    }
    __syncthreads();

    int i0 = (t >> 4) << 3, j0 = (t & 15) << 2;   // 8 rows x 4 cols per thread
    float acc[8][4];
#pragma unroll
    for (int r = 0; r < 8; r++)
#pragma unroll
        for (int c = 0; c < 4; c++) acc[r][c] = 0.f;

    for (int k = 0; k < 64; k++) {
        float av[8];
        *(float4*)(av)     = *(const float4*)&As[k][i0];
        *(float4*)(av + 4) = *(const float4*)&As[k][i0 + 4];
        float4 bv = *(const float4*)&Bs[k][j0];
#pragma unroll
        for (int r = 0; r < 8; r++) {
            acc[r][0] = fmaf(av[r], bv.x, acc[r][0]);
            acc[r][1] = fmaf(av[r], bv.y, acc[r][1]);
            acc[r][2] = fmaf(av[r], bv.z, acc[r][2]);
            acc[r][3] = fmaf(av[r], bv.w, acc[r][3]);
        }
    }
    __syncthreads();
#pragma unroll
    for (int r = 0; r < 8; r++)
#pragma unroll
        for (int c = 0; c < 4; c++) As[i0 + r][j0 + c] = acc[r][c];
    __syncthreads();

    __nv_bfloat16* dstN = g_pairs  + mId * 4096;
    __nv_bfloat16* dstT = g_pairsT + mId * 4096;
#pragma unroll
    for (int q = 0; q < 4; q++) {
        int g = t + 128 * q;              // granule id 0..511
        int c = g >> 6, j = g & 63;
        uint4 u;
        u.x = packbf(As[8 * c + 0][j], As[8 * c + 1][j]);
        u.y = packbf(As[8 * c + 2][j], As[8 * c + 3][j]);
        u.z = packbf(As[8 * c + 4][j], As[8 * c + 5][j]);
        u.w = packbf(As[8 * c + 6][j], As[8 * c + 7][j]);
        *(uint4*)(dstN + c * 512 + j * 8) = u;
        int i = g & 63, cT = g >> 6;
        const float* rp = &As[i][8 * cT];
        uint4 v;
        v.x = packbf(rp[0], rp[1]);
        v.y = packbf(rp[2], rp[3]);
        v.z = packbf(rp[4], rp[5]);
        v.w = packbf(rp[6], rp[7]);
        *(uint4*)(dstT + cT * 512 + i * 8) = v;
    }
}

// ---------------------------------------------------------------------------
// Kernel 3: bidirectional forward, 2 sequences per CTA (static longest-with-
// shortest pairing). 148 CTAs x 256 threads = 4 independent 64-thread groups:
//   tid   0- 63: seqA left    (bar 1)     tid  64-127: seqA right (bar 2)
//   tid 128-191: seqB left    (bar 3)     tid 192-255: seqB right (bar 4)
// One thread per column, 8 k-chunks, f32x2 packed math.
// ---------------------------------------------------------------------------
__device__ __forceinline__ void ffma2(unsigned long long& acc, unsigned u,
                                      unsigned long long p2) {
    asm("{\n\t"
        ".reg .b32 wl, wh;\n\t"
        ".reg .b64 w2;\n\t"
        "shl.b32 wl, %1, 16;\n\t"
        "and.b32 wh, %1, 0xFFFF0000;\n\t"
        "mov.b64 w2, {wl, wh};\n\t"
        "fma.rn.f32x2 %0, w2, %2, %0;\n\t"
        "}" : "+l"(acc) : "r"(u), "l"(p2));
}
__device__ __forceinline__ unsigned long long addx2(unsigned long long a,
                                                    unsigned long long b) {
    unsigned long long r;
    asm("add.rn.f32x2 %0, %1, %2;" : "=l"(r) : "l"(a), "l"(b));
    return r;
}
__device__ __forceinline__ void unpack2(unsigned long long a, float& lo, float& hi) {
    asm("mov.b64 {%0, %1}, %2;" : "=f"(lo), "=f"(hi) : "l"(a));
}

#define LOADW(W, T_)                                                           \
    {                                                                          \
        int off_ = midx[(T_)];                                                 \
        const uint4* b_ =                                                      \
            ((off_ & 1) ? singles : pairs) + ((off_ & ~1) >> 3) + j;           \
        _Pragma("unroll")                                                      \
        for (int c_ = 0; c_ < 8; c_++) (W)[c_] = __ldg(b_ + c_ * 64);          \
    }

// Step order: LDS p first (right after bar), ffma, THEN prefetch LDGs (their
// wavefronts drain during the following STS+bar instead of ahead of the LDS).
#define STEPD(W)                                                               \
    {                                                                          \
        const ulonglong2* pc_ = (const ulonglong2*)psm[t & 1];                 \
        unsigned long long A_ = 0ull, B_ = 0ull, C_ = 0ull, D_ = 0ull;         \
        _Pragma("unroll")                                                      \
        for (int c_ = 0; c_ < 8; c_++) {                                       \
            ulonglong2 p0_ = pc_[2 * c_];                                      \
            ulonglong2 p1_ = pc_[2 * c_ + 1];                                  \
            uint4 u_ = (W)[c_];                                                \
            ffma2(A_, u_.x, p0_.x);                                            \
            ffma2(B_, u_.y, p0_.y);                                            \
            ffma2(C_, u_.z, p1_.x);                                            \
            ffma2(D_, u_.w, p1_.y);                                            \
        }                                                                      \
        if (t + 2 < nsteps) LOADW(W, t + 2);                                   \
        A_ = addx2(A_, B_);                                                    \
        C_ = addx2(C_, D_);                                                    \
        A_ = addx2(A_, C_);                                                    \
        float lo_, hi_;                                                        \
        unpack2(A_, lo_, hi_);                                                 \
        psm[(t + 1) & 1][j] = lo_ + hi_;                                       \
        asm volatile("bar.sync %0, 64;" :: "r"(barid) : "memory");             \
        t++;                                                                   \
    }

__device__ __forceinline__ void run_dir(const uint4* __restrict__ pairs,
                                        const uint4* __restrict__ singles,
                                        const int* midx, int nsteps,
                                        float (*psm)[QN], int j, int barid) {
    uint4 w0[8], w1[8];
    if (nsteps > 0) LOADW(w0, 0);
    if (nsteps > 1) LOADW(w1, 1);
    int t = 0;
    while (t < nsteps) {
        STEPD(w0);
        if (t >= nsteps) break;
        STEPD(w1);
    }
}

__global__ void __launch_bounds__(256, 1)
k_forward(const int* __restrict__ x, const int* __restrict__ lengths,
          const float* __restrict__ f_logits, float* __restrict__ out) {
    __shared__ __align__(16) float pL[2][2][QN];   // [slot][buf][col]
    __shared__ __align__(16) float pR[2][2][QN];
    __shared__ __align__(16) float ef[QN];         // exp(f - M)
    __shared__ int midxA[2][MAXSTEP];              // [slot][step] left
    __shared__ int midxB[2][MAXSTEP];              // [slot][step] right
    __shared__ float red[2][4];
    __shared__ float prep[4];
    __shared__ float sLogS2;

    int tid = threadIdx.x;

    // ---- hoisted f_logits prep ----
    if (tid < 64) {
        float f = __ldg(f_logits + tid);
        float Mv = f;
#pragma unroll
        for (int o = 16; o; o >>= 1) Mv = fmaxf(Mv, __shfl_xor_sync(0xFFFFFFFFu, Mv, o));
        if ((tid & 31) == 0) prep[tid >> 5] = Mv;
        asm volatile("bar.sync 7, 64;" ::: "memory");
        float M = fmaxf(prep[0], prep[1]);
        float e = expf(f - M);
        ef[tid] = e;
        float S2 = e;
#pragma unroll
        for (int o = 16; o; o >>= 1) S2 += __shfl_xor_sync(0xFFFFFFFFu, S2, o);
        if ((tid & 31) == 0) prep[2 + (tid >> 5)] = S2;
        asm volatile("bar.sync 7, 64;" ::: "memory");
        if (tid == 0) sLogS2 = logf(prep[2] + prep[3]);
    }
    __syncthreads();

    // ---- static assignment: slot0 = rank cta, slot1 = rank 255-cta ----
    int slot = tid >> 7;            // 0 or 1
    int tid7 = tid & 127;           // id within sequence group
    int cta = blockIdx.x;
    int rank = slot == 0 ? cta : (BN - 1 - cta);
    if (slot == 1 && rank < 148) return;          // no second sequence
    int b = g_order[rank];

    int L = __ldg(lengths + b);
    int np  = L >> 1;
    int npL = (np + 1) >> 1;
    int npR = np - npL;
    int odd = L & 1;
    int stepsR = npR + odd;
    int m = 2 * npL;
    const int* xb = x + b * SN;
    int* midxL = midxA[slot];
    int* midxR = midxB[slot];

    for (int t = tid7; t < npL; t += 128)
        midxL[t] = (__ldg(xb + 2 * t) * 32 + __ldg(xb + 2 * t + 1)) * 4096;
    for (int s2 = tid7; s2 < stepsR; s2 += 128) {
        int off;
        if (odd && s2 == 0) {
            off = __ldg(xb + L - 1) * 4096 | 1;
        } else {
            int k = npR - 1 - (s2 - odd);
            off = (__ldg(xb + m + 2 * k) * 32 + __ldg(xb + m + 2 * k + 1)) * 4096;
        }
        midxR[s2] = off;
    }
    if (tid7 < 64) pL[slot][0][tid7] = (tid7 == 0) ? 1.0f : 0.0f;
    else           pR[slot][0][tid7 - 64] = ef[tid7 - 64];
    // full-sequence barrier (128 threads): bars 5 (slot0), 6 (slot1)
    asm volatile("bar.sync %0, 128;" :: "r"(5 + slot) : "memory");

    int dir = tid7 >> 6;            // 0 = left, 1 = right
    int barid = 1 + 2 * slot + dir; // 1,2 (slot0), 3,4 (slot1)
    if (dir == 0)
        run_dir((const uint4*)g_pairs,  (const uint4*)g_singles,  midxL, npL,
                pL[slot], tid7, barid);
    else
        run_dir((const uint4*)g_pairsT, (const uint4*)g_singlesT, midxR, stepsR,
                pR[slot], tid7 - 64, barid);
    asm volatile("bar.sync %0, 128;" :: "r"(5 + slot) : "memory");

    // combine (left group of each slot: 64 threads, bar 1/3)
    if (tid7 < 64) {
        int wid = tid7 >> 5;
        float a = pL[slot][npL & 1][tid7];
        float r = pR[slot][stepsR & 1][tid7];
        float d = a * r, sa = a;
#pragma unroll
        for (int o = 16; o; o >>= 1) {
            d  += __shfl_xor_sync(0xFFFFFFFFu, d,  o);
            sa += __shfl_xor_sync(0xFFFFFFFFu, sa, o);
        }
        if ((tid7 & 31) == 0) { red[slot][wid] = d; red[slot][2 + wid] = sa; }
        asm volatile("bar.sync %0, 64;" :: "r"(1 + 2 * slot) : "memory");
        if (tid7 == 0)
            out[b] = logf(red[slot][0] + red[slot][1])
                   - logf(red[slot][2] + red[slot][3]) - sLogS2;
    }
}

extern "C" void kernel_launch(void* const* d_in, const int* in_sizes, int n_in,
                              void* d_out, int out_size) {
    const int*   x        = (const int*)d_in[0];       // [256, 2048]
    const int*   lengths  = (const int*)d_in[1];       // [256]
    const float* T_logits = (const float*)d_in[2];     // [64, 32, 64]
    const float* f_logits = (const float*)d_in[3];     // [64]
    float* out = (float*)d_out;                        // [256]

    k_softmax<<<512, 128>>>(T_logits);
    k_sort<<<1, BN>>>(lengths);
    k_pairs<<<1024, 128>>>();
    k_forward<<<148, 256>>>(x, lengths, f_logits, out);
}